// round 17
// baseline (speedup 1.0000x reference)
#include <cuda_runtime.h>

// ---------------------------------------------------------------------------
// 2-layer LSTM (H=51), T=2048 + 16 autoregressive steps, B=512.
// R17 = R10 (best: 3653us) + COMPILE-TIME BUFFER PARITY:
// the tick body is a macro with parity as literal constants and the tau loop
// unrolled x2 -> all double-buffer smem addresses become immediate offsets
// (no per-load IMAD, no address-dependency stall before LDS.128).
// Input/output marched with running pointers.
// Roles (exactly R10):
//   L1  (thr   0..203): gate1(tau)    = b1 + Wih1*x + Whh1 . h1(tau-1), owns c1
//   L2A (thr 204..407): gate2a(tau-1) = b2 + Wih2 . h1(tau-1), owns c2
//   L2B (thr 408..611): gate2b(tau-1) =      Whh2 . h2(tau-2)
//   spares (612..619) : out-dot(tau-2), x-prefetch(tau+1)
// 2 barriers per tick. Serial 5-phase epilogue for the 16 future steps.
// ---------------------------------------------------------------------------

#define H     51
#define G4    204
#define T     2048
#define FUT   16
#define TT    (T + FUT)
#define NB    4
#define NBLK  128
#define WPAD  52          // h row pitch (float; h[51] = 0)
#define G1P   208
#define G2P   416         // two partials per gate: col 2g / 2g+1
#define NTH   640         // 20 warps

typedef unsigned long long u64;

__device__ __forceinline__ u64 pack2(float lo, float hi) {
    u64 r; asm("mov.b64 %0, {%1,%2};" : "=l"(r) : "f"(lo), "f"(hi)); return r;
}
__device__ __forceinline__ u64 ffma2(u64 a, u64 b, u64 c) {
    u64 d; asm("fma.rn.f32x2 %0, %1, %2, %3;" : "=l"(d) : "l"(a), "l"(b), "l"(c));
    return d;
}
__device__ __forceinline__ float hsum2(u64 a) {
    float lo, hi; asm("mov.b64 {%0,%1}, %2;" : "=f"(lo), "=f"(hi) : "l"(a));
    return lo + hi;
}
__device__ __forceinline__ float sigf(float x) {
    return __fdividef(1.f, 1.f + __expf(-x));
}
__device__ __forceinline__ float tanh_fast(float x) {
    float xc = fminf(fmaxf(x, -15.f), 15.f);
    float e  = __expf(2.f * xc);
    return __fdividef(e - 1.f, e + 1.f);
}
__device__ __forceinline__ float lstm_act(float gi, float gf, float gg, float go, float& c) {
    c = sigf(gf) * c + sigf(gi) * tanh_fast(gg);
    return sigf(go) * tanh_fast(c);
}

struct __align__(16) Smem {
    float h1[2][NB][WPAD];   // h1(s) in slot s&1 (pad col 51 = 0)
    float h2[2][NB][WPAD];
    float G1[NB][G1P];       // layer-1 gates
    float G2[NB][G2P];       // layer-2 partials at cols 2g / 2g+1
    float WL[WPAD];          // W_lin padded
    float X[2][NB];          // x(s) in slot s&1
    float OUTB[NB];
    float blin;
};

// the one dot shape every worker runs: 13 float4 chunks x 4 batches
__device__ __forceinline__ void dot13(const float* __restrict__ hb,
                                      const u64* __restrict__ w, u64* acc) {
    #pragma unroll
    for (int c = 0; c < 13; c++) {
        #pragma unroll
        for (int b = 0; b < NB; b++) {
            ulonglong2 hv = *(const ulonglong2*)(hb + b * WPAD + 4 * c);
            acc[b] = ffma2(w[2 * c],     hv.x, acc[b]);
            acc[b] = ffma2(w[2 * c + 1], hv.y, acc[b]);
        }
    }
}

__global__ __launch_bounds__(NTH, 1)
void lstm_ct_kernel(const float* __restrict__ input,
                    const float* __restrict__ Wih1,
                    const float* __restrict__ Whh1,
                    const float* __restrict__ bih1,
                    const float* __restrict__ bhh1,
                    const float* __restrict__ Wih2,
                    const float* __restrict__ Whh2,
                    const float* __restrict__ bih2,
                    const float* __restrict__ bhh2,
                    const float* __restrict__ Wlin,
                    const float* __restrict__ blin,
                    float* __restrict__ out)
{
    __shared__ Smem s;
    const int j   = threadIdx.x;
    const int bb0 = blockIdx.x * NB;

    const int  ro   = (j < 204) ? 0 : (j < 408 ? 1 : (j < 612 ? 2 : 3));
    const bool isW  = (ro < 3);
    const int  row  = (ro == 0) ? j : (ro == 1 ? j - 204 : (ro == 2 ? j - 408 : 0));
    const bool isOut = (j >= 612 && j < 616);
    const bool isX   = (j >= 616 && j < 620);

    // ---------------- prologue: one weight row per worker ----------------
    u64 wreg[26];
    float bj = 0.f, wi1 = 0.f;
    if (isW) {
        const float* wsrc = (ro == 0) ? (Whh1 + row * H)
                          : (ro == 1) ? (Wih2 + row * H)
                                      : (Whh2 + row * H);
        #pragma unroll
        for (int p = 0; p < 26; p++) {
            int k1 = 2 * p + 1;
            wreg[p] = pack2(wsrc[2 * p], (k1 < H) ? wsrc[k1] : 0.f);
        }
        if (ro == 0) { bj = bih1[row] + bhh1[row]; wi1 = Wih1[row]; }
        if (ro == 1) { bj = bih2[row] + bhh2[row]; }
    }
    const int b1 = isW ? (row / H) : 0;
    const int u1 = isW ? (row % H) : 0;
    float cc = 0.f;                       // c1 for ro0, c2 for ro1

    // running pointers for the service lanes
    const float* xp = isX  ? (input + (size_t)(bb0 + (j - 616)) * T + 1) : input;
    float*       op = isOut ? (out  + (size_t)(bb0 + (j - 612)) * TT)    : out;

    // init shared state
    for (int idx = j; idx < 2 * NB * WPAD; idx += NTH) {
        (&s.h1[0][0][0])[idx] = 0.f;
        (&s.h2[0][0][0])[idx] = 0.f;
    }
    if (j < WPAD) s.WL[j] = (j < H) ? Wlin[j] : 0.f;
    if (j < NB) {
        s.X[0][j]  = input[(size_t)(bb0 + j) * T];
        s.X[1][j]  = 0.f;
        s.OUTB[j]  = 0.f;
    }
    if (j == 0) s.blin = blin[0];
    __syncthreads();

    // ------------- tick body: PA/PB are LITERAL constants -------------
#define TICK(TAU, PA, PB) do {                                                \
        const int  tau_   = (TAU);                                           \
        const bool l1act_ = (tau_ < T);                                      \
        const bool l2act_ = (tau_ >= 1 && tau_ <= T);                        \
        float xr_ = 0.f;                                                     \
        if (isW && ((ro == 0) ? l1act_ : l2act_)) {                          \
            u64 acc[NB];                                                     \
            if (ro == 0) {                                                   \
                _Pragma("unroll")                                            \
                for (int b = 0; b < NB; b++)                                 \
                    acc[b] = pack2(fmaf(wi1, s.X[PA][b], bj), 0.f);          \
            } else {                                                         \
                _Pragma("unroll")                                            \
                for (int b = 0; b < NB; b++) acc[b] = pack2(bj, 0.f);        \
            }                                                                \
            const float* hb = (ro == 2) ? &s.h2[PA][0][0] : &s.h1[PB][0][0]; \
            dot13(hb, wreg, acc);                                            \
            if (ro == 0) {                                                   \
                _Pragma("unroll")                                            \
                for (int b = 0; b < NB; b++) s.G1[b][row] = hsum2(acc[b]);   \
            } else {                                                         \
                _Pragma("unroll")                                            \
                for (int b = 0; b < NB; b++)                                 \
                    s.G2[b][2 * row + (ro - 1)] = hsum2(acc[b]);             \
            }                                                                \
        }                                                                    \
        if (isOut && tau_ >= 2) {                                            \
            const int b_ = j - 612;                                          \
            float a0 = 0.f, a1 = 0.f, a2 = 0.f, a3 = 0.f;                    \
            const float* h2p = &s.h2[PA][b_][0];                             \
            _Pragma("unroll")                                                \
            for (int p = 0; p < 13; p++) {                                   \
                float4 w = *(const float4*)&s.WL[4 * p];                     \
                float4 h = *(const float4*)&h2p[4 * p];                      \
                a0 = fmaf(w.x, h.x, a0);  a1 = fmaf(w.y, h.y, a1);           \
                a2 = fmaf(w.z, h.z, a2);  a3 = fmaf(w.w, h.w, a3);           \
            }                                                                \
            float val = (a0 + a1) + (a2 + a3) + s.blin;                      \
            op[tau_ - 2] = val;                                              \
            s.OUTB[b_] = val;                                                \
        }                                                                    \
        if (isX && tau_ <= T - 2) xr_ = xp[tau_];                            \
        __syncthreads();                                                     \
        if (ro == 0 && l1act_) {                                             \
            float gi = s.G1[b1][u1],         gf = s.G1[b1][H + u1];          \
            float gg = s.G1[b1][2 * H + u1], go = s.G1[b1][3 * H + u1];      \
            s.h1[PA][b1][u1] = lstm_act(gi, gf, gg, go, cc);                 \
        }                                                                    \
        if (ro == 1 && l2act_) {                                             \
            float2 vi = *(const float2*)&s.G2[b1][2 * u1];                   \
            float2 vf = *(const float2*)&s.G2[b1][2 * (H + u1)];             \
            float2 vg = *(const float2*)&s.G2[b1][2 * (2 * H + u1)];         \
            float2 vo = *(const float2*)&s.G2[b1][2 * (3 * H + u1)];         \
            s.h2[PB][b1][u1] = lstm_act(vi.x + vi.y, vf.x + vf.y,            \
                                        vg.x + vg.y, vo.x + vo.y, cc);       \
        }                                                                    \
        if (isX && tau_ <= T - 2) s.X[PB][j - 616] = xr_;                    \
        __syncthreads();                                                     \
    } while (0)

    // --------------------------- pipelined main loop ---------------------------
    #pragma unroll 1
    for (int tau = 0; tau <= T + 1; tau += 2) {
        TICK(tau,     0, 1);
        TICK(tau + 1, 1, 0);
    }
#undef TICK

    // --------------------- serial autoregressive epilogue ---------------------
    for (int t = T; t < TT; t++) {
        const int pA = t & 1, pB = pA ^ 1;

        if (ro == 0 && isW) {                      // gate1, x = previous output
            u64 acc[NB];
            #pragma unroll
            for (int b = 0; b < NB; b++)
                acc[b] = pack2(fmaf(wi1, s.OUTB[b], bj), 0.f);
            dot13(&s.h1[pB][0][0], wreg, acc);
            #pragma unroll
            for (int b = 0; b < NB; b++) s.G1[b][row] = hsum2(acc[b]);
        }
        __syncthreads();
        if (ro == 0 && isW) {
            float gi = s.G1[b1][u1],         gf = s.G1[b1][H + u1];
            float gg = s.G1[b1][2 * H + u1], go = s.G1[b1][3 * H + u1];
            s.h1[pA][b1][u1] = lstm_act(gi, gf, gg, go, cc);
        }
        __syncthreads();
        if (isW && ro != 0) {                      // gate2 of step t
            u64 acc[NB];
            #pragma unroll
            for (int b = 0; b < NB; b++) acc[b] = pack2(bj, 0.f);
            const float* hb = (ro == 1) ? &s.h1[pA][0][0] : &s.h2[pB][0][0];
            dot13(hb, wreg, acc);
            #pragma unroll
            for (int b = 0; b < NB; b++) s.G2[b][2 * row + (ro - 1)] = hsum2(acc[b]);
        }
        __syncthreads();
        if (ro == 1 && isW) {
            float2 vi = *(const float2*)&s.G2[b1][2 * u1];
            float2 vf = *(const float2*)&s.G2[b1][2 * (H + u1)];
            float2 vg = *(const float2*)&s.G2[b1][2 * (2 * H + u1)];
            float2 vo = *(const float2*)&s.G2[b1][2 * (3 * H + u1)];
            s.h2[pA][b1][u1] = lstm_act(vi.x + vi.y, vf.x + vf.y,
                                        vg.x + vg.y, vo.x + vo.y, cc);
        }
        __syncthreads();
        if (isOut) {                               // out(t) -> gmem + OUTB
            const int b = j - 612;
            float a0 = 0.f, a1 = 0.f, a2 = 0.f, a3 = 0.f;
            const float* h2p = &s.h2[pA][b][0];
            #pragma unroll
            for (int p = 0; p < 13; p++) {
                float4 w = *(const float4*)&s.WL[4 * p];
                float4 h = *(const float4*)&h2p[4 * p];
                a0 = fmaf(w.x, h.x, a0);  a1 = fmaf(w.y, h.y, a1);
                a2 = fmaf(w.z, h.z, a2);  a3 = fmaf(w.w, h.w, a3);
            }
            float val = (a0 + a1) + (a2 + a3) + s.blin;
            op[t] = val;
            s.OUTB[b] = val;
        }
        __syncthreads();
    }
}

extern "C" void kernel_launch(void* const* d_in, const int* in_sizes, int n_in,
                              void* d_out, int out_size)
{
    const float* input = (const float*)d_in[0];
    const float* Wih1  = (const float*)d_in[1];
    const float* Whh1  = (const float*)d_in[2];
    const float* bih1  = (const float*)d_in[3];
    const float* bhh1  = (const float*)d_in[4];
    const float* Wih2  = (const float*)d_in[5];
    const float* Whh2  = (const float*)d_in[6];
    const float* bih2  = (const float*)d_in[7];
    const float* bhh2  = (const float*)d_in[8];
    const float* Wlin  = (const float*)d_in[9];
    const float* blin  = (const float*)d_in[10];
    float* out = (float*)d_out;

    lstm_ct_kernel<<<NBLK, NTH>>>(
        input, Wih1, Whh1, bih1, bhh1, Wih2, Whh2, bih2, bhh2, Wlin, blin, out);
}